// round 1
// baseline (speedup 1.0000x reference)
#include <cuda_runtime.h>

#define NH 16
#define DK 64
#define NC 32
#define SL 16
#define B_ 32
#define TL 512
#define DM 1024

// Scratch (static device globals — allowed; no runtime allocation)
__device__ float g_qs[NH * NC * SL * DK];            // [z][c][s][h]
__device__ float g_wql[NC * DM];                     // [c][n]
__device__ float g_wkt[(size_t)B_ * NH * DK * TL];   // [b][z][h][t]  (64 MB)
__device__ float g_partial[B_ * NH * NC];            // [b][z][c]

__device__ __forceinline__ float fast_tanhf(float x) {
    float xc = fminf(fmaxf(x, -15.0f), 15.0f);
    float e = __expf(2.0f * xc);
    return __fdividef(e - 1.0f, e + 1.0f);
}

// C[m,n] = sum_k A[m,k] * B[n,k]   (A: MxK row-major, B: 1024x1024 row-major weights)
// MODE 0: store to g_qs   (m = c*16+s, n = z*64+h)
// MODE 1: store tanh(C) to g_wkt [b][z][h][t]  (m = b*512+t, n = z*64+h)
// MODE 2: store to g_wql row-major
template <int MODE>
__global__ __launch_bounds__(256) void gemm_nt(const float* __restrict__ A,
                                               const float* __restrict__ Bm, int M) {
    __shared__ float As[16 * 132];
    __shared__ float Bs[16 * 132];
    const int tid = threadIdx.x;
    const int tx = tid & 15, ty = tid >> 4;
    const int n0 = blockIdx.x * 128, m0 = blockIdx.y * 128;
    const int lr = tid >> 2, lq = tid & 3;

    float acc[8][8];
#pragma unroll
    for (int i = 0; i < 8; i++)
#pragma unroll
        for (int j = 0; j < 8; j++) acc[i][j] = 0.0f;

    for (int k0 = 0; k0 < DM; k0 += 16) {
#pragma unroll
        for (int half = 0; half < 2; half++) {
            int r = lr + half * 64;
            int m = m0 + r;
            float4 av = make_float4(0.f, 0.f, 0.f, 0.f);
            if (m < M) av = *(const float4*)(A + (size_t)m * DM + k0 + lq * 4);
            As[(lq * 4 + 0) * 132 + r] = av.x;
            As[(lq * 4 + 1) * 132 + r] = av.y;
            As[(lq * 4 + 2) * 132 + r] = av.z;
            As[(lq * 4 + 3) * 132 + r] = av.w;
            float4 bv = *(const float4*)(Bm + (size_t)(n0 + r) * DM + k0 + lq * 4);
            Bs[(lq * 4 + 0) * 132 + r] = bv.x;
            Bs[(lq * 4 + 1) * 132 + r] = bv.y;
            Bs[(lq * 4 + 2) * 132 + r] = bv.z;
            Bs[(lq * 4 + 3) * 132 + r] = bv.w;
        }
        __syncthreads();
#pragma unroll
        for (int k = 0; k < 16; k++) {
            float4 a0 = *(const float4*)(As + k * 132 + ty * 4);
            float4 a1 = *(const float4*)(As + k * 132 + 64 + ty * 4);
            float4 b0 = *(const float4*)(Bs + k * 132 + tx * 4);
            float4 b1 = *(const float4*)(Bs + k * 132 + 64 + tx * 4);
            float a[8] = {a0.x, a0.y, a0.z, a0.w, a1.x, a1.y, a1.z, a1.w};
            float b[8] = {b0.x, b0.y, b0.z, b0.w, b1.x, b1.y, b1.z, b1.w};
#pragma unroll
            for (int i = 0; i < 8; i++)
#pragma unroll
                for (int j = 0; j < 8; j++) acc[i][j] = fmaf(a[i], b[j], acc[i][j]);
        }
        __syncthreads();
    }

#pragma unroll
    for (int i = 0; i < 8; i++) {
        int mi = (i < 4) ? (ty * 4 + i) : (64 + ty * 4 + i - 4);
        int m = m0 + mi;
        if (m >= M) continue;
#pragma unroll
        for (int j = 0; j < 8; j++) {
            int nj = (j < 4) ? (tx * 4 + j) : (64 + tx * 4 + j - 4);
            int n = n0 + nj;
            float v = acc[i][j];
            if (MODE == 0) {
                int c = m >> 4, s = m & 15, z = n >> 6, h = n & 63;
                g_qs[((z * NC + c) * SL + s) * DK + h] = v;
            } else if (MODE == 1) {
                int b = m >> 9, t = m & 511, z = n >> 6, h = n & 63;
                g_wkt[(size_t)(b * NH + z) * DK * TL + h * TL + t] = fast_tanhf(v);
            } else {
                g_wql[m * DM + n] = v;
            }
        }
    }
}

// Shared-memory layout for attention kernel (floats)
#define SM_WKT 0
#define SM_KW (64 * 512)
#define SM_Q (SM_KW + 32 * 512)
#define SM_WQL (SM_Q + 4 * 16 * 64)
#define SM_RED (SM_WQL + 32 * 64)
#define ATTN_SMEM_BYTES ((SM_RED + 64) * 4)

// One CTA per (b, z). 512 threads = 16 warps; warp w handles synonym row s=w.
// Classes processed 4 at a time (register-blocked).
__global__ __launch_bounds__(512) void attn_kernel(const float* __restrict__ H) {
    extern __shared__ float sm[];
    float* sWKT = sm + SM_WKT;  // [h][t]   64x512
    float* sKW = sm + SM_KW;    // [c][t]   32x512
    float* sQ = sm + SM_Q;      // [cc][s][h] 4x16x64
    float* sWql = sm + SM_WQL;  // [c][h]   32x64
    float* sRed = sm + SM_RED;  // [16][4]

    const int z = blockIdx.x, b = blockIdx.y;
    const int tid = threadIdx.x;
    const int lane = tid & 31, w = tid >> 5;

    // Load tanh(k_s) slice [h][t] for this (b,z): contiguous 128 KB
    {
        const float4* src = (const float4*)(g_wkt + (size_t)(b * NH + z) * DK * TL);
        float4* dst = (float4*)sWKT;
#pragma unroll
        for (int i = 0; i < 16; i++) dst[tid + i * 512] = src[tid + i * 512];
    }
    // Load Wql head slice [c][h]
    for (int i = tid; i < NC * DK; i += 512) {
        int c = i >> 6, h = i & 63;
        sWql[i] = g_wql[c * DM + z * DK + h];
    }
    __syncthreads();

    // KW[c][t] = sum_h tanh(H[b,t,z*64+h]) * Wql[c, z*64+h]   (thread t = tid)
    {
        const int t = tid;
        float kv[64];
        const float* hp = H + ((size_t)(b * TL + t)) * DM + z * DK;
#pragma unroll
        for (int h = 0; h < 64; h++) kv[h] = fast_tanhf(hp[h]);
        for (int c = 0; c < NC; c++) {
            float a = 0.f;
#pragma unroll
            for (int h = 0; h < 64; h++) a = fmaf(kv[h], sWql[c * DK + h], a);
            sKW[c * TL + t] = a;
        }
    }

    for (int g = 0; g < 8; g++) {
        __syncthreads();  // sKW ready (g=0) / sRed consumed, sQ free (g>0)
        const int c0 = g * 4;
#pragma unroll
        for (int i2 = 0; i2 < 8; i2++) {
            int i = tid + i2 * 512;
            int cc = i >> 10;
            sQ[i] = g_qs[(z * NC + c0 + cc) * (SL * DK) + (i & 1023)];
        }
        __syncthreads();

        // scores: acc[cc][k*4+j] = score(t = k*128 + lane*4 + j) for s-row w
        float acc[4][16];
#pragma unroll
        for (int cc = 0; cc < 4; cc++)
#pragma unroll
            for (int k = 0; k < 16; k++) acc[cc][k] = 0.f;

#pragma unroll 4
        for (int h = 0; h < 64; h++) {
            float4 wk0 = *(const float4*)(sWKT + h * TL + 0 * 128 + lane * 4);
            float4 wk1 = *(const float4*)(sWKT + h * TL + 1 * 128 + lane * 4);
            float4 wk2 = *(const float4*)(sWKT + h * TL + 2 * 128 + lane * 4);
            float4 wk3 = *(const float4*)(sWKT + h * TL + 3 * 128 + lane * 4);
#pragma unroll
            for (int cc = 0; cc < 4; cc++) {
                float q = sQ[cc * 1024 + w * 64 + h];
                acc[cc][0] = fmaf(wk0.x, q, acc[cc][0]);
                acc[cc][1] = fmaf(wk0.y, q, acc[cc][1]);
                acc[cc][2] = fmaf(wk0.z, q, acc[cc][2]);
                acc[cc][3] = fmaf(wk0.w, q, acc[cc][3]);
                acc[cc][4] = fmaf(wk1.x, q, acc[cc][4]);
                acc[cc][5] = fmaf(wk1.y, q, acc[cc][5]);
                acc[cc][6] = fmaf(wk1.z, q, acc[cc][6]);
                acc[cc][7] = fmaf(wk1.w, q, acc[cc][7]);
                acc[cc][8] = fmaf(wk2.x, q, acc[cc][8]);
                acc[cc][9] = fmaf(wk2.y, q, acc[cc][9]);
                acc[cc][10] = fmaf(wk2.z, q, acc[cc][10]);
                acc[cc][11] = fmaf(wk2.w, q, acc[cc][11]);
                acc[cc][12] = fmaf(wk3.x, q, acc[cc][12]);
                acc[cc][13] = fmaf(wk3.y, q, acc[cc][13]);
                acc[cc][14] = fmaf(wk3.z, q, acc[cc][14]);
                acc[cc][15] = fmaf(wk3.w, q, acc[cc][15]);
            }
        }

        // softmax (row = full warp: 16 regs x 32 lanes = 512 t) + dot with KW
#pragma unroll
        for (int cc = 0; cc < 4; cc++) {
            float mx = acc[cc][0];
#pragma unroll
            for (int k = 1; k < 16; k++) mx = fmaxf(mx, acc[cc][k]);
#pragma unroll
            for (int off = 16; off >= 1; off >>= 1)
                mx = fmaxf(mx, __shfl_xor_sync(0xffffffffu, mx, off));

            float l = 0.f, v = 0.f;
#pragma unroll
            for (int k = 0; k < 4; k++) {
                float4 kw = *(const float4*)(sKW + (c0 + cc) * TL + k * 128 + lane * 4);
                float p0 = __expf(acc[cc][k * 4 + 0] - mx);
                float p1 = __expf(acc[cc][k * 4 + 1] - mx);
                float p2 = __expf(acc[cc][k * 4 + 2] - mx);
                float p3 = __expf(acc[cc][k * 4 + 3] - mx);
                l += p0 + p1 + p2 + p3;
                v = fmaf(p0, kw.x, v);
                v = fmaf(p1, kw.y, v);
                v = fmaf(p2, kw.z, v);
                v = fmaf(p3, kw.w, v);
            }
#pragma unroll
            for (int off = 16; off >= 1; off >>= 1) {
                l += __shfl_xor_sync(0xffffffffu, l, off);
                v += __shfl_xor_sync(0xffffffffu, v, off);
            }
            if (lane == 0) sRed[w * 4 + cc] = __fdividef(v, l);
        }
        __syncthreads();
        if (tid < 4) {
            float s = 0.f;
#pragma unroll
            for (int ww = 0; ww < 16; ww++) s += sRed[ww * 4 + tid];
            g_partial[(b * NH + z) * NC + c0 + tid] = s * (1.0f / 16.0f);
        }
    }
}

__global__ void reduce_out(float* __restrict__ out) {
    int tid = threadIdx.x;  // 1024 = b*32 + c
    int b = tid >> 5, c = tid & 31;
    float s = 0.f;
#pragma unroll
    for (int zz = 0; zz < NH; zz++) s += g_partial[(b * NH + zz) * NC + c];
    out[tid] = s;
}

extern "C" void kernel_launch(void* const* d_in, const int* in_sizes, int n_in,
                              void* d_out, int out_size) {
    const float* Q = (const float*)d_in[0];
    const float* H = (const float*)d_in[1];
    const float* ql = (const float*)d_in[2];
    const float* WQ = (const float*)d_in[3];
    const float* WK = (const float*)d_in[4];
    const float* WV = (const float*)d_in[5];
    float* out = (float*)d_out;

    cudaFuncSetAttribute(attn_kernel, cudaFuncAttributeMaxDynamicSharedMemorySize,
                         ATTN_SMEM_BYTES);

    gemm_nt<0><<<dim3(8, 4), 256>>>(Q, WQ, NC * SL);      // q_s
    gemm_nt<2><<<dim3(8, 1), 256>>>(ql, WV, NC);          // Wql
    gemm_nt<1><<<dim3(8, 128), 256>>>(H, WK, B_ * TL);    // tanh(k_s), head-major
    attn_kernel<<<dim3(NH, B_), 512, ATTN_SMEM_BYTES>>>(H);
    reduce_out<<<1, 1024>>>(out);
}

// round 2
// speedup vs baseline: 1.6476x; 1.6476x over previous
#include <cuda_runtime.h>
#include <cuda_bf16.h>
#include <cstdint>

#define NH 16
#define DK 64
#define NC 32
#define SL 16
#define B_ 32
#define TL 512
#define DM 1024

// Scratch (static device globals — allowed; no runtime allocation)
__device__ float g_qs[NH * NC * SL * DK];            // [z][c][s][h]
__device__ float g_wql[NC * DM];                     // [c][n]
__device__ float g_wkt[(size_t)B_ * NH * DK * TL];   // [b][z][h][t]  (64 MB)
__device__ float g_partial[B_ * NH * NC];            // [b][z][c]
__device__ __nv_bfloat16 g_hbf[(size_t)B_ * TL * DM];  // 32 MB
__device__ __nv_bfloat16 g_wkbf[DM * DM];              // 2 MB

__device__ __forceinline__ float fast_tanhf(float x) {
    float xc = fminf(fmaxf(x, -15.0f), 15.0f);
    float e = __expf(2.0f * xc);
    return __fdividef(e - 1.0f, e + 1.0f);
}

__device__ __forceinline__ uint32_t smem_u32(const void* p) {
    return (uint32_t)__cvta_generic_to_shared(p);
}

// ---------------- fp32 -> bf16 conversion ----------------
__global__ __launch_bounds__(256) void cvt_bf16_kernel(const float4* __restrict__ in,
                                                       __nv_bfloat162* __restrict__ out,
                                                       int n4) {
    int i = blockIdx.x * blockDim.x + threadIdx.x;
    if (i < n4) {
        float4 v = in[i];
        out[2 * i] = __floats2bfloat162_rn(v.x, v.y);
        out[2 * i + 1] = __floats2bfloat162_rn(v.z, v.w);
    }
}

// ---------------- small fp32 GEMMs (q_s, Wql) ----------------
// C[m,n] = sum_k A[m,k] * B[n,k]
// MODE 0: store to g_qs   (m = c*16+s, n = z*64+h)
// MODE 2: store to g_wql row-major
template <int MODE>
__global__ __launch_bounds__(256) void gemm_nt(const float* __restrict__ A,
                                               const float* __restrict__ Bm, int M) {
    __shared__ float As[16 * 132];
    __shared__ float Bs[16 * 132];
    const int tid = threadIdx.x;
    const int tx = tid & 15, ty = tid >> 4;
    const int n0 = blockIdx.x * 128, m0 = blockIdx.y * 128;
    const int lr = tid >> 2, lq = tid & 3;

    float acc[8][8];
#pragma unroll
    for (int i = 0; i < 8; i++)
#pragma unroll
        for (int j = 0; j < 8; j++) acc[i][j] = 0.0f;

    for (int k0 = 0; k0 < DM; k0 += 16) {
#pragma unroll
        for (int half = 0; half < 2; half++) {
            int r = lr + half * 64;
            int m = m0 + r;
            float4 av = make_float4(0.f, 0.f, 0.f, 0.f);
            if (m < M) av = *(const float4*)(A + (size_t)m * DM + k0 + lq * 4);
            As[(lq * 4 + 0) * 132 + r] = av.x;
            As[(lq * 4 + 1) * 132 + r] = av.y;
            As[(lq * 4 + 2) * 132 + r] = av.z;
            As[(lq * 4 + 3) * 132 + r] = av.w;
            float4 bv = *(const float4*)(Bm + (size_t)(n0 + r) * DM + k0 + lq * 4);
            Bs[(lq * 4 + 0) * 132 + r] = bv.x;
            Bs[(lq * 4 + 1) * 132 + r] = bv.y;
            Bs[(lq * 4 + 2) * 132 + r] = bv.z;
            Bs[(lq * 4 + 3) * 132 + r] = bv.w;
        }
        __syncthreads();
#pragma unroll
        for (int k = 0; k < 16; k++) {
            float4 a0 = *(const float4*)(As + k * 132 + ty * 4);
            float4 a1 = *(const float4*)(As + k * 132 + 64 + ty * 4);
            float4 b0 = *(const float4*)(Bs + k * 132 + tx * 4);
            float4 b1 = *(const float4*)(Bs + k * 132 + 64 + tx * 4);
            float a[8] = {a0.x, a0.y, a0.z, a0.w, a1.x, a1.y, a1.z, a1.w};
            float b[8] = {b0.x, b0.y, b0.z, b0.w, b1.x, b1.y, b1.z, b1.w};
#pragma unroll
            for (int i = 0; i < 8; i++)
#pragma unroll
                for (int j = 0; j < 8; j++) acc[i][j] = fmaf(a[i], b[j], acc[i][j]);
        }
        __syncthreads();
    }

#pragma unroll
    for (int i = 0; i < 8; i++) {
        int mi = (i < 4) ? (ty * 4 + i) : (64 + ty * 4 + i - 4);
        int m = m0 + mi;
        if (m >= M) continue;
#pragma unroll
        for (int j = 0; j < 8; j++) {
            int nj = (j < 4) ? (tx * 4 + j) : (64 + tx * 4 + j - 4);
            int n = n0 + nj;
            float v = acc[i][j];
            if (MODE == 0) {
                int c = m >> 4, s = m & 15, z = n >> 6, h = n & 63;
                g_qs[((z * NC + c) * SL + s) * DK + h] = v;
            } else {
                g_wql[m * DM + n] = v;
            }
        }
    }
}

// ---------------- bf16 tensor-core GEMM for the K projection ----------------
// C[16384,1024] = Hbf @ WKbf^T, epilogue: tanh -> g_wkt[b][z][h][t]
// CTA tile 128x128, k-tile 64 (128B rows, SW128 swizzle), 3-stage cp.async.
#define GSTAGES 3
#define STAGE_BYTES 32768  // A 16KB + B 16KB

__device__ __forceinline__ void cp_async16(uint32_t dst, const void* src) {
    asm volatile("cp.async.cg.shared.global [%0], [%1], 16;\n" ::"r"(dst), "l"(src));
}

__device__ __forceinline__ void ldsm_x4(uint32_t* r, uint32_t addr) {
    asm volatile("ldmatrix.sync.aligned.m8n8.x4.shared.b16 {%0,%1,%2,%3}, [%4];"
                 : "=r"(r[0]), "=r"(r[1]), "=r"(r[2]), "=r"(r[3])
                 : "r"(addr));
}

__device__ __forceinline__ void mma16816(float* c, const uint32_t* a, uint32_t b0,
                                         uint32_t b1) {
    asm volatile(
        "mma.sync.aligned.m16n8k16.row.col.f32.bf16.bf16.f32 "
        "{%0,%1,%2,%3}, {%4,%5,%6,%7}, {%8,%9}, {%0,%1,%2,%3};"
        : "+f"(c[0]), "+f"(c[1]), "+f"(c[2]), "+f"(c[3])
        : "r"(a[0]), "r"(a[1]), "r"(a[2]), "r"(a[3]), "r"(b0), "r"(b1));
}

__device__ __forceinline__ void load_gemm_tile(uint32_t sA, uint32_t sB,
                                               const __nv_bfloat16* gA,
                                               const __nv_bfloat16* gB, int m0, int n0,
                                               int kt, int tid) {
#pragma unroll
    for (int i = 0; i < 4; i++) {
        int cid = tid + i * 256;          // 0..1023
        int row = cid >> 3, c = cid & 7;  // 128 rows x 8 chunks of 16B
        uint32_t off = row * 128 + ((c * 16) ^ ((row & 7) << 4));
        cp_async16(sA + off, gA + (size_t)(m0 + row) * DM + kt * 64 + c * 8);
        cp_async16(sB + off, gB + (size_t)(n0 + row) * DM + kt * 64 + c * 8);
    }
}

__global__ __launch_bounds__(256, 2) void gemm_bf16_tanh(
    const __nv_bfloat16* __restrict__ A, const __nv_bfloat16* __restrict__ Bm) {
    extern __shared__ char smem_raw[];
    const int m0 = blockIdx.y * 128, n0 = blockIdx.x * 128;
    const int tid = threadIdx.x;
    const int lane = tid & 31, wid = tid >> 5;
    const int warp_m = wid & 1, warp_n = wid >> 1;  // 2 x 4 warps -> 64M x 32N each
    const uint32_t sbase = smem_u32(smem_raw);

    float acc[4][4][4];
#pragma unroll
    for (int i = 0; i < 4; i++)
#pragma unroll
        for (int j = 0; j < 4; j++)
#pragma unroll
            for (int r = 0; r < 4; r++) acc[i][j][r] = 0.f;

    // per-lane swizzled fragment base offsets
    const int rA = lane & 15;
    const int selA = (lane >= 16) ? 16 : 0;
    uint32_t pA[4];
#pragma unroll
    for (int mf = 0; mf < 4; mf++) {
        int row = warp_m * 64 + mf * 16 + rA;
        pA[mf] = row * 128 + (selA ^ ((row & 7) << 4));
    }
    const int rB = (lane & 7) + ((lane >= 16) ? 8 : 0);
    const int selB = (lane & 8) ? 16 : 0;
    uint32_t pB[2];
#pragma unroll
    for (int np = 0; np < 2; np++) {
        int row = warp_n * 32 + np * 16 + rB;
        pB[np] = row * 128 + (selB ^ ((row & 7) << 4));
    }

    // prologue: fill STAGES-1 stages
#pragma unroll
    for (int s = 0; s < GSTAGES - 1; s++) {
        load_gemm_tile(sbase + s * STAGE_BYTES, sbase + s * STAGE_BYTES + 16384, A, Bm,
                       m0, n0, s, tid);
        asm volatile("cp.async.commit_group;");
    }

    const int NT = DM / 64;  // 16
    for (int kt = 0; kt < NT; kt++) {
        asm volatile("cp.async.wait_group %0;" ::"n"(GSTAGES - 2));
        __syncthreads();
        uint32_t sA = sbase + (kt % GSTAGES) * STAGE_BYTES;
        uint32_t sB = sA + 16384;
#pragma unroll
        for (int ks = 0; ks < 4; ks++) {
            uint32_t af[4][4], bb[2][4];
#pragma unroll
            for (int mf = 0; mf < 4; mf++) ldsm_x4(af[mf], sA + (pA[mf] ^ (ks << 5)));
#pragma unroll
            for (int np = 0; np < 2; np++) ldsm_x4(bb[np], sB + (pB[np] ^ (ks << 5)));
#pragma unroll
            for (int mf = 0; mf < 4; mf++)
#pragma unroll
                for (int nf = 0; nf < 4; nf++)
                    mma16816(acc[mf][nf], af[mf], bb[nf >> 1][(nf & 1) * 2],
                             bb[nf >> 1][(nf & 1) * 2 + 1]);
        }
        int kn = kt + GSTAGES - 1;
        if (kn < NT) {
            uint32_t s = sbase + (kn % GSTAGES) * STAGE_BYTES;
            load_gemm_tile(s, s + 16384, A, Bm, m0, n0, kn, tid);
        }
        asm volatile("cp.async.commit_group;");
    }

    // epilogue: tanh + scatter to g_wkt[b][z][h][t]
    const int gid = lane >> 2, tig = lane & 3;
#pragma unroll
    for (int mf = 0; mf < 4; mf++) {
#pragma unroll
        for (int nf = 0; nf < 4; nf++) {
            int m = m0 + warp_m * 64 + mf * 16 + gid;
            int n = n0 + warp_n * 32 + nf * 8 + tig * 2;
#pragma unroll
            for (int rh = 0; rh < 2; rh++) {  // row half: +0 / +8
                int mm = m + rh * 8;
                int b = mm >> 9, t = mm & 511;
#pragma unroll
                for (int cc = 0; cc < 2; cc++) {
                    int nn = n + cc;
                    int z = nn >> 6, h = nn & 63;
                    float v = acc[mf][nf][rh * 2 + cc];
                    g_wkt[(size_t)((b * NH + z) * DK + h) * TL + t] = fast_tanhf(v);
                }
            }
        }
    }
}

// ---------------- attention ----------------
#define SM_WKT 0
#define SM_KW (64 * 512)
#define SM_Q (SM_KW + 32 * 512)
#define SM_WQL (SM_Q + 4 * 16 * 64)
#define SM_RED (SM_WQL + 32 * 64)
#define ATTN_SMEM_BYTES ((SM_RED + 64) * 4)

__global__ __launch_bounds__(512) void attn_kernel(const float* __restrict__ H) {
    extern __shared__ float sm[];
    float* sWKT = sm + SM_WKT;
    float* sKW = sm + SM_KW;
    float* sQ = sm + SM_Q;
    float* sWql = sm + SM_WQL;
    float* sRed = sm + SM_RED;

    const int z = blockIdx.x, b = blockIdx.y;
    const int tid = threadIdx.x;
    const int lane = tid & 31, w = tid >> 5;

    {
        const float4* src = (const float4*)(g_wkt + (size_t)(b * NH + z) * DK * TL);
        float4* dst = (float4*)sWKT;
#pragma unroll
        for (int i = 0; i < 16; i++) dst[tid + i * 512] = src[tid + i * 512];
    }
    for (int i = tid; i < NC * DK; i += 512) {
        int c = i >> 6, h = i & 63;
        sWql[i] = g_wql[c * DM + z * DK + h];
    }
    __syncthreads();

    {
        const int t = tid;
        float kv[64];
        const float* hp = H + ((size_t)(b * TL + t)) * DM + z * DK;
#pragma unroll
        for (int h = 0; h < 64; h++) kv[h] = fast_tanhf(hp[h]);
        for (int c = 0; c < NC; c++) {
            float a = 0.f;
#pragma unroll
            for (int h = 0; h < 64; h++) a = fmaf(kv[h], sWql[c * DK + h], a);
            sKW[c * TL + t] = a;
        }
    }

    for (int g = 0; g < 8; g++) {
        __syncthreads();
        const int c0 = g * 4;
#pragma unroll
        for (int i2 = 0; i2 < 8; i2++) {
            int i = tid + i2 * 512;
            int cc = i >> 10;
            sQ[i] = g_qs[(z * NC + c0 + cc) * (SL * DK) + (i & 1023)];
        }
        __syncthreads();

        float acc[4][16];
#pragma unroll
        for (int cc = 0; cc < 4; cc++)
#pragma unroll
            for (int k = 0; k < 16; k++) acc[cc][k] = 0.f;

#pragma unroll 4
        for (int h = 0; h < 64; h++) {
            float4 wk0 = *(const float4*)(sWKT + h * TL + 0 * 128 + lane * 4);
            float4 wk1 = *(const float4*)(sWKT + h * TL + 1 * 128 + lane * 4);
            float4 wk2 = *(const float4*)(sWKT + h * TL + 2 * 128 + lane * 4);
            float4 wk3 = *(const float4*)(sWKT + h * TL + 3 * 128 + lane * 4);
#pragma unroll
            for (int cc = 0; cc < 4; cc++) {
                float q = sQ[cc * 1024 + w * 64 + h];
                acc[cc][0] = fmaf(wk0.x, q, acc[cc][0]);
                acc[cc][1] = fmaf(wk0.y, q, acc[cc][1]);
                acc[cc][2] = fmaf(wk0.z, q, acc[cc][2]);
                acc[cc][3] = fmaf(wk0.w, q, acc[cc][3]);
                acc[cc][4] = fmaf(wk1.x, q, acc[cc][4]);
                acc[cc][5] = fmaf(wk1.y, q, acc[cc][5]);
                acc[cc][6] = fmaf(wk1.z, q, acc[cc][6]);
                acc[cc][7] = fmaf(wk1.w, q, acc[cc][7]);
                acc[cc][8] = fmaf(wk2.x, q, acc[cc][8]);
                acc[cc][9] = fmaf(wk2.y, q, acc[cc][9]);
                acc[cc][10] = fmaf(wk2.z, q, acc[cc][10]);
                acc[cc][11] = fmaf(wk2.w, q, acc[cc][11]);
                acc[cc][12] = fmaf(wk3.x, q, acc[cc][12]);
                acc[cc][13] = fmaf(wk3.y, q, acc[cc][13]);
                acc[cc][14] = fmaf(wk3.z, q, acc[cc][14]);
                acc[cc][15] = fmaf(wk3.w, q, acc[cc][15]);
            }
        }

#pragma unroll
        for (int cc = 0; cc < 4; cc++) {
            float mx = acc[cc][0];
#pragma unroll
            for (int k = 1; k < 16; k++) mx = fmaxf(mx, acc[cc][k]);
#pragma unroll
            for (int off = 16; off >= 1; off >>= 1)
                mx = fmaxf(mx, __shfl_xor_sync(0xffffffffu, mx, off));

            float l = 0.f, v = 0.f;
#pragma unroll
            for (int k = 0; k < 4; k++) {
                float4 kw = *(const float4*)(sKW + (c0 + cc) * TL + k * 128 + lane * 4);
                float p0 = __expf(acc[cc][k * 4 + 0] - mx);
                float p1 = __expf(acc[cc][k * 4 + 1] - mx);
                float p2 = __expf(acc[cc][k * 4 + 2] - mx);
                float p3 = __expf(acc[cc][k * 4 + 3] - mx);
                l += p0 + p1 + p2 + p3;
                v = fmaf(p0, kw.x, v);
                v = fmaf(p1, kw.y, v);
                v = fmaf(p2, kw.z, v);
                v = fmaf(p3, kw.w, v);
            }
#pragma unroll
            for (int off = 16; off >= 1; off >>= 1) {
                l += __shfl_xor_sync(0xffffffffu, l, off);
                v += __shfl_xor_sync(0xffffffffu, v, off);
            }
            if (lane == 0) sRed[w * 4 + cc] = __fdividef(v, l);
        }
        __syncthreads();
        if (tid < 4) {
            float s = 0.f;
#pragma unroll
            for (int ww = 0; ww < 16; ww++) s += sRed[ww * 4 + tid];
            g_partial[(b * NH + z) * NC + c0 + tid] = s * (1.0f / 16.0f);
        }
    }
}

__global__ void reduce_out(float* __restrict__ out) {
    int tid = threadIdx.x;
    int b = tid >> 5, c = tid & 31;
    float s = 0.f;
#pragma unroll
    for (int zz = 0; zz < NH; zz++) s += g_partial[(b * NH + zz) * NC + c];
    out[tid] = s;
}

extern "C" void kernel_launch(void* const* d_in, const int* in_sizes, int n_in,
                              void* d_out, int out_size) {
    const float* Q = (const float*)d_in[0];
    const float* H = (const float*)d_in[1];
    const float* ql = (const float*)d_in[2];
    const float* WQ = (const float*)d_in[3];
    const float* WK = (const float*)d_in[4];
    const float* WV = (const float*)d_in[5];
    float* out = (float*)d_out;

    cudaFuncSetAttribute(attn_kernel, cudaFuncAttributeMaxDynamicSharedMemorySize,
                         ATTN_SMEM_BYTES);
    cudaFuncSetAttribute(gemm_bf16_tanh, cudaFuncAttributeMaxDynamicSharedMemorySize,
                         GSTAGES * STAGE_BYTES);

    __nv_bfloat16* hbf;
    __nv_bfloat16* wkbf;
    cudaGetSymbolAddress((void**)&hbf, g_hbf);
    cudaGetSymbolAddress((void**)&wkbf, g_wkbf);

    // fp32 -> bf16 conversions
    cvt_bf16_kernel<<<(B_ * TL * DM / 4 + 255) / 256, 256>>>(
        (const float4*)H, (__nv_bfloat162*)hbf, B_ * TL * DM / 4);
    cvt_bf16_kernel<<<(DM * DM / 4 + 255) / 256, 256>>>(
        (const float4*)WK, (__nv_bfloat162*)wkbf, DM * DM / 4);

    gemm_nt<0><<<dim3(8, 4), 256>>>(Q, WQ, NC * SL);  // q_s (fp32)
    gemm_nt<2><<<dim3(8, 1), 256>>>(ql, WV, NC);      // Wql (fp32)
    gemm_bf16_tanh<<<dim3(8, 128), 256, GSTAGES * STAGE_BYTES>>>(hbf, wkbf);
    attn_kernel<<<dim3(NH, B_), 512, ATTN_SMEM_BYTES>>>(H);
    reduce_out<<<1, 1024>>>(out);
}

// round 3
// speedup vs baseline: 4.0420x; 2.4532x over previous
#include <cuda_runtime.h>
#include <cuda_bf16.h>
#include <cstdint>

#define NH 16
#define DK 64
#define NC 32
#define SL 16
#define B_ 32
#define TL 512
#define DM 1024

// Scratch (static device globals — no runtime allocation)
__device__ float g_wql[NC * DM];                         // [c][n] fp32
__device__ float g_wqlp[4 * NC * DM];                    // split-K partials
__device__ float g_partial[B_ * NH * NC];                // [b][z][c]
__device__ __nv_bfloat16 g_hbf[(size_t)B_ * TL * DM];    // H bf16 (32 MB)
__device__ __nv_bfloat16 g_wkbf[DM * DM];                // WK bf16
__device__ __nv_bfloat16 g_wqbf[DM * DM];                // WQ bf16
__device__ __nv_bfloat16 g_qbf[NC * SL * DM];            // Q bf16
__device__ __nv_bfloat16 g_wktb[(size_t)B_ * NH * TL * DK];  // tanh(k_s) [b][z][t][h]
__device__ __nv_bfloat16 g_qsb[NH * NC * SL * DK];           // q_s [z][cs][h]

__device__ __forceinline__ float fast_tanhf(float x) {
    float xc = fminf(fmaxf(x, -15.0f), 15.0f);
    float e = __expf(2.0f * xc);
    return __fdividef(e - 1.0f, e + 1.0f);
}

__device__ __forceinline__ uint32_t smem_u32(const void* p) {
    return (uint32_t)__cvta_generic_to_shared(p);
}

__device__ __forceinline__ void cp_async16(uint32_t dst, const void* src) {
    asm volatile("cp.async.cg.shared.global [%0], [%1], 16;\n" ::"r"(dst), "l"(src));
}

__device__ __forceinline__ void ldsm_x4(uint32_t* r, uint32_t addr) {
    asm volatile("ldmatrix.sync.aligned.m8n8.x4.shared.b16 {%0,%1,%2,%3}, [%4];"
                 : "=r"(r[0]), "=r"(r[1]), "=r"(r[2]), "=r"(r[3])
                 : "r"(addr));
}

__device__ __forceinline__ void mma16816(float* c, const uint32_t* a, uint32_t b0,
                                         uint32_t b1) {
    asm volatile(
        "mma.sync.aligned.m16n8k16.row.col.f32.bf16.bf16.f32 "
        "{%0,%1,%2,%3}, {%4,%5,%6,%7}, {%8,%9}, {%0,%1,%2,%3};"
        : "+f"(c[0]), "+f"(c[1]), "+f"(c[2]), "+f"(c[3])
        : "r"(a[0]), "r"(a[1]), "r"(a[2]), "r"(a[3]), "r"(b0), "r"(b1));
}

// ---------------- fp32 -> bf16 conversion ----------------
__global__ __launch_bounds__(256) void cvt_bf16_kernel(const float4* __restrict__ in,
                                                       __nv_bfloat162* __restrict__ out,
                                                       int n4) {
    int i = blockIdx.x * blockDim.x + threadIdx.x;
    if (i < n4) {
        float4 v = in[i];
        out[2 * i] = __floats2bfloat162_rn(v.x, v.y);
        out[2 * i + 1] = __floats2bfloat162_rn(v.z, v.w);
    }
}

// ---------------- Wql = ql @ WV^T  (fp32, split-K, deterministic) ----------------
__global__ __launch_bounds__(128) void wql_partial(const float* __restrict__ ql,
                                                   const float* __restrict__ WV) {
    __shared__ float sql[32 * 256];
    const int nb = blockIdx.x, kb = blockIdx.y;
    const int tid = threadIdx.x;
#pragma unroll
    for (int j = 0; j < 16; j++) {
        int idx = tid + j * 128;  // float4 id 0..2047
        int c = idx >> 6, q = idx & 63;
        *(float4*)(sql + c * 256 + q * 4) =
            *(const float4*)(ql + c * DM + kb * 256 + q * 4);
    }
    __syncthreads();
    const int n = nb * 128 + tid;
    float acc[32];
#pragma unroll
    for (int c = 0; c < 32; c++) acc[c] = 0.f;
    const float4* wv = (const float4*)(WV + (size_t)n * DM + kb * 256);
#pragma unroll 4
    for (int k4 = 0; k4 < 64; k4++) {
        float4 w = wv[k4];
#pragma unroll
        for (int c = 0; c < 32; c++) {
            float4 qv = *(const float4*)(sql + c * 256 + k4 * 4);
            acc[c] = fmaf(w.x, qv.x, acc[c]);
            acc[c] = fmaf(w.y, qv.y, acc[c]);
            acc[c] = fmaf(w.z, qv.z, acc[c]);
            acc[c] = fmaf(w.w, qv.w, acc[c]);
        }
    }
#pragma unroll
    for (int c = 0; c < 32; c++) g_wqlp[(kb * NC + c) * DM + n] = acc[c];
}

__global__ void wql_reduce() {  // grid 32 (c), 1024 threads (n)
    int c = blockIdx.x, n = threadIdx.x;
    g_wql[c * DM + n] = ((g_wqlp[(0 * NC + c) * DM + n] + g_wqlp[(1 * NC + c) * DM + n]) +
                         (g_wqlp[(2 * NC + c) * DM + n] + g_wqlp[(3 * NC + c) * DM + n]));
}

// ---------------- bf16 tensor-core GEMM, C = A @ B^T ----------------
// MODE 0: q_s  -> g_qsb bf16 [z][m][h]
// MODE 1: tanh(k_s) -> g_wktb bf16 [b][z][t][h]
#define GSTAGES 3
#define STAGE_BYTES 32768

__device__ __forceinline__ void load_gemm_tile(uint32_t sA, uint32_t sB,
                                               const __nv_bfloat16* gA,
                                               const __nv_bfloat16* gB, int m0, int n0,
                                               int kt, int tid) {
#pragma unroll
    for (int i = 0; i < 4; i++) {
        int cid = tid + i * 256;
        int row = cid >> 3, c = cid & 7;
        uint32_t off = row * 128 + ((c * 16) ^ ((row & 7) << 4));
        cp_async16(sA + off, gA + (size_t)(m0 + row) * DM + kt * 64 + c * 8);
        cp_async16(sB + off, gB + (size_t)(n0 + row) * DM + kt * 64 + c * 8);
    }
}

template <int MODE>
__global__ __launch_bounds__(256, 2) void gemm_bf16(const __nv_bfloat16* __restrict__ A,
                                                    const __nv_bfloat16* __restrict__ Bm) {
    extern __shared__ char smem_raw[];
    const int m0 = blockIdx.y * 128, n0 = blockIdx.x * 128;
    const int tid = threadIdx.x;
    const int lane = tid & 31, wid = tid >> 5;
    const int warp_m = wid & 1, warp_n = wid >> 1;
    const uint32_t sbase = smem_u32(smem_raw);

    float acc[4][4][4];
#pragma unroll
    for (int i = 0; i < 4; i++)
#pragma unroll
        for (int j = 0; j < 4; j++)
#pragma unroll
            for (int r = 0; r < 4; r++) acc[i][j][r] = 0.f;

    const int rA = lane & 15;
    const int selA = (lane >= 16) ? 16 : 0;
    uint32_t pA[4];
#pragma unroll
    for (int mf = 0; mf < 4; mf++) {
        int row = warp_m * 64 + mf * 16 + rA;
        pA[mf] = row * 128 + (selA ^ ((row & 7) << 4));
    }
    const int rB = (lane & 7) + ((lane >= 16) ? 8 : 0);
    const int selB = (lane & 8) ? 16 : 0;
    uint32_t pB[2];
#pragma unroll
    for (int np = 0; np < 2; np++) {
        int row = warp_n * 32 + np * 16 + rB;
        pB[np] = row * 128 + (selB ^ ((row & 7) << 4));
    }

#pragma unroll
    for (int s = 0; s < GSTAGES - 1; s++) {
        load_gemm_tile(sbase + s * STAGE_BYTES, sbase + s * STAGE_BYTES + 16384, A, Bm,
                       m0, n0, s, tid);
        asm volatile("cp.async.commit_group;");
    }

    const int NT = DM / 64;
    for (int kt = 0; kt < NT; kt++) {
        asm volatile("cp.async.wait_group %0;" ::"n"(GSTAGES - 2));
        __syncthreads();
        uint32_t sA = sbase + (kt % GSTAGES) * STAGE_BYTES;
        uint32_t sB = sA + 16384;
#pragma unroll
        for (int ks = 0; ks < 4; ks++) {
            uint32_t af[4][4], bb[2][4];
#pragma unroll
            for (int mf = 0; mf < 4; mf++) ldsm_x4(af[mf], sA + (pA[mf] ^ (ks << 5)));
#pragma unroll
            for (int np = 0; np < 2; np++) ldsm_x4(bb[np], sB + (pB[np] ^ (ks << 5)));
#pragma unroll
            for (int mf = 0; mf < 4; mf++)
#pragma unroll
                for (int nf = 0; nf < 4; nf++)
                    mma16816(acc[mf][nf], af[mf], bb[nf >> 1][(nf & 1) * 2],
                             bb[nf >> 1][(nf & 1) * 2 + 1]);
        }
        int kn = kt + GSTAGES - 1;
        if (kn < NT) {
            uint32_t s = sbase + (kn % GSTAGES) * STAGE_BYTES;
            load_gemm_tile(s, s + 16384, A, Bm, m0, n0, kn, tid);
        }
        asm volatile("cp.async.commit_group;");
    }

    const int gid = lane >> 2, tig = lane & 3;
#pragma unroll
    for (int mf = 0; mf < 4; mf++) {
#pragma unroll
        for (int nf = 0; nf < 4; nf++) {
            int m = m0 + warp_m * 64 + mf * 16 + gid;
            int n = n0 + warp_n * 32 + nf * 8 + tig * 2;
            int z = n >> 6, h = n & 63;
#pragma unroll
            for (int rh = 0; rh < 2; rh++) {
                int mm = m + rh * 8;
                float v0 = acc[mf][nf][rh * 2 + 0];
                float v1 = acc[mf][nf][rh * 2 + 1];
                if (MODE == 1) {
                    int b = mm >> 9, t = mm & 511;
                    __nv_bfloat162 o = __floats2bfloat162_rn(fast_tanhf(v0), fast_tanhf(v1));
                    *(__nv_bfloat162*)(g_wktb + ((size_t)((b * NH + z) * TL + t)) * DK + h) = o;
                } else {
                    __nv_bfloat162 o = __floats2bfloat162_rn(v0, v1);
                    *(__nv_bfloat162*)(g_qsb + ((size_t)(z * (NC * SL) + mm)) * DK + h) = o;
                }
            }
        }
    }
}

// ---------------- attention: tensor-core scores + single-pass softmax ----------------
// One CTA per (b, z). 512 thr = 16 warps; warp w owns classes 2w, 2w+1 (32 rows of S).
#define ATTN_SMEM (65536 * 3 + 8192)

__global__ __launch_bounds__(512, 1) void attn_kernel(const float* __restrict__ H) {
    extern __shared__ char sm[];
    __nv_bfloat16* sWKb = (__nv_bfloat16*)sm;            // [t][h] swizzled, 64 KB
    __nv_bfloat16* sQb = (__nv_bfloat16*)(sm + 65536);   // [cs][h] swizzled, 64 KB
    float* sKW = (float*)(sm + 131072);                  // [c][512], 64 KB
    float* sWql = (float*)(sm + 196608);                 // [c][64], 8 KB

    const int z = blockIdx.x, b = blockIdx.y;
    const int tid = threadIdx.x, lane = tid & 31, w = tid >> 5;
    const uint32_t sWK_u = smem_u32(sWKb), sQ_u = smem_u32(sQb);

    {
        const char* gwk = (const char*)(g_wktb + (size_t)(b * NH + z) * TL * DK);
        const char* gq = (const char*)(g_qsb + (size_t)z * (NC * SL) * DK);
#pragma unroll
        for (int i = 0; i < 8; i++) {
            int cid = tid + i * 512;
            int row = cid >> 3, cc = cid & 7;
            uint32_t off = row * 128 + ((cc * 16) ^ ((row & 7) << 4));
            cp_async16(sWK_u + off, gwk + row * 128 + cc * 16);
            cp_async16(sQ_u + off, gq + row * 128 + cc * 16);
        }
        int c = tid >> 4, q = tid & 15;
        cp_async16(smem_u32(sWql) + tid * 16, g_wql + c * DM + z * DK + q * 4);
        asm volatile("cp.async.commit_group;");
        asm volatile("cp.async.wait_group 0;");
    }
    __syncthreads();

    // KW[c][t] = sum_h tanh(H[b,t,z*64+h]) * Wql[c, z*64+h]
    {
        const int t = tid;
        float kv[64];
        const float* hp = H + ((size_t)(b * TL + t)) * DM + z * DK;
#pragma unroll
        for (int h = 0; h < 64; h++) kv[h] = fast_tanhf(hp[h]);
        for (int c = 0; c < NC; c++) {
            float a = 0.f;
#pragma unroll
            for (int h = 0; h < 64; h++) a = fmaf(kv[h], sWql[c * DK + h], a);
            sKW[c * TL + t] = a;
        }
    }
    __syncthreads();

    // A fragments: rows 32w .. 32w+31 of q_s (k = h, 4 k-steps), held in regs
    uint32_t afr[2][4][4];
    {
        const int rA = lane & 15;
        const int selA = (lane >= 16) ? 16 : 0;
#pragma unroll
        for (int mf = 0; mf < 2; mf++) {
            int row = w * 32 + mf * 16 + rA;
            uint32_t p = row * 128 + (selA ^ ((row & 7) << 4));
#pragma unroll
            for (int ks = 0; ks < 4; ks++) ldsm_x4(afr[mf][ks], sQ_u + (p ^ (ks << 5)));
        }
    }

    const int rB = (lane & 7) + ((lane >= 16) ? 8 : 0);
    const int selB = (lane & 8) ? 16 : 0;
    const int tig = lane & 3;

    float l[2][2] = {{0.f, 0.f}, {0.f, 0.f}};
    float v[2][2] = {{0.f, 0.f}, {0.f, 0.f}};

    for (int tc = 0; tc < 16; tc++) {  // t chunks of 32
        float acc[2][4][4];
#pragma unroll
        for (int mf = 0; mf < 2; mf++)
#pragma unroll
            for (int nf = 0; nf < 4; nf++)
#pragma unroll
                for (int r = 0; r < 4; r++) acc[mf][nf][r] = 0.f;

#pragma unroll
        for (int ks = 0; ks < 4; ks++) {
            uint32_t bb[2][4];
#pragma unroll
            for (int np = 0; np < 2; np++) {
                int row = tc * 32 + np * 16 + rB;
                uint32_t p = row * 128 + (selB ^ ((row & 7) << 4));
                ldsm_x4(bb[np], sWK_u + (p ^ (ks << 5)));
            }
#pragma unroll
            for (int mf = 0; mf < 2; mf++)
#pragma unroll
                for (int nf = 0; nf < 4; nf++)
                    mma16816(acc[mf][nf], afr[mf][ks], bb[nf >> 1][(nf & 1) * 2],
                             bb[nf >> 1][(nf & 1) * 2 + 1]);
        }

        // exp + accumulate l, v = sum p*KW (scores tiny: no max-subtract needed;
        // softmax ratio is mathematically identical)
#pragma unroll
        for (int mf = 0; mf < 2; mf++) {
            const float* kwrow = sKW + (2 * w + mf) * TL + tc * 32;
#pragma unroll
            for (int nf = 0; nf < 4; nf++) {
                float2 kw = *(const float2*)(kwrow + nf * 8 + tig * 2);
#pragma unroll
                for (int rh = 0; rh < 2; rh++) {
                    float p0 = __expf(acc[mf][nf][rh * 2 + 0]);
                    float p1 = __expf(acc[mf][nf][rh * 2 + 1]);
                    l[mf][rh] += p0 + p1;
                    v[mf][rh] = fmaf(p0, kw.x, fmaf(p1, kw.y, v[mf][rh]));
                }
            }
        }
    }

    // per-row v/l, then mean over s (16 rows per class), write g_partial
#pragma unroll
    for (int mf = 0; mf < 2; mf++) {
        float r = 0.f;
#pragma unroll
        for (int rh = 0; rh < 2; rh++) {
            float ll = l[mf][rh], vv = v[mf][rh];
#pragma unroll
            for (int off = 1; off <= 2; off <<= 1) {
                ll += __shfl_xor_sync(0xffffffffu, ll, off);
                vv += __shfl_xor_sync(0xffffffffu, vv, off);
            }
            r += __fdividef(vv, ll);
        }
#pragma unroll
        for (int off = 4; off <= 16; off <<= 1) r += __shfl_xor_sync(0xffffffffu, r, off);
        if (lane == 0) g_partial[(b * NH + z) * NC + 2 * w + mf] = r * (1.0f / 16.0f);
    }
}

__global__ void reduce_out(float* __restrict__ out) {
    int tid = threadIdx.x;
    int b = tid >> 5, c = tid & 31;
    float s = 0.f;
#pragma unroll
    for (int zz = 0; zz < NH; zz++) s += g_partial[(b * NH + zz) * NC + c];
    out[tid] = s;
}

extern "C" void kernel_launch(void* const* d_in, const int* in_sizes, int n_in,
                              void* d_out, int out_size) {
    const float* Q = (const float*)d_in[0];
    const float* H = (const float*)d_in[1];
    const float* ql = (const float*)d_in[2];
    const float* WQ = (const float*)d_in[3];
    const float* WK = (const float*)d_in[4];
    const float* WV = (const float*)d_in[5];
    float* out = (float*)d_out;

    cudaFuncSetAttribute(attn_kernel, cudaFuncAttributeMaxDynamicSharedMemorySize,
                         ATTN_SMEM);
    cudaFuncSetAttribute(gemm_bf16<0>, cudaFuncAttributeMaxDynamicSharedMemorySize,
                         GSTAGES * STAGE_BYTES);
    cudaFuncSetAttribute(gemm_bf16<1>, cudaFuncAttributeMaxDynamicSharedMemorySize,
                         GSTAGES * STAGE_BYTES);

    __nv_bfloat16 *hbf, *wkbf, *wqbf, *qbf;
    cudaGetSymbolAddress((void**)&hbf, g_hbf);
    cudaGetSymbolAddress((void**)&wkbf, g_wkbf);
    cudaGetSymbolAddress((void**)&wqbf, g_wqbf);
    cudaGetSymbolAddress((void**)&qbf, g_qbf);

    cvt_bf16_kernel<<<(B_ * TL * DM / 4 + 255) / 256, 256>>>(
        (const float4*)H, (__nv_bfloat162*)hbf, B_ * TL * DM / 4);
    cvt_bf16_kernel<<<(DM * DM / 4 + 255) / 256, 256>>>(
        (const float4*)WK, (__nv_bfloat162*)wkbf, DM * DM / 4);
    cvt_bf16_kernel<<<(DM * DM / 4 + 255) / 256, 256>>>(
        (const float4*)WQ, (__nv_bfloat162*)wqbf, DM * DM / 4);
    cvt_bf16_kernel<<<(NC * SL * DM / 4 + 255) / 256, 256>>>(
        (const float4*)Q, (__nv_bfloat162*)qbf, NC * SL * DM / 4);

    wql_partial<<<dim3(8, 4), 128>>>(ql, WV);
    wql_reduce<<<32, 1024>>>();

    gemm_bf16<0><<<dim3(8, 4), 256, GSTAGES * STAGE_BYTES>>>(qbf, wqbf);
    gemm_bf16<1><<<dim3(8, 128), 256, GSTAGES * STAGE_BYTES>>>(hbf, wkbf);

    attn_kernel<<<dim3(NH, B_), 512, ATTN_SMEM>>>(H);
    reduce_out<<<1, 1024>>>(out);
}

// round 5
// speedup vs baseline: 6.0296x; 1.4917x over previous
#include <cuda_runtime.h>
#include <cuda_bf16.h>
#include <cuda_fp16.h>
#include <cstdint>

#define NH 16
#define DK 64
#define NC 32
#define SL 16
#define B_ 32
#define TL 512
#define DM 1024

// Scratch (static device globals — no runtime allocation)
__device__ float g_wql[NC * DM];                         // [c][n] fp32
__device__ float g_wqlp[4 * NC * DM];                    // split-K partials
__device__ float g_partial[B_ * NH * NC];                // [b][z][c]
__device__ __nv_bfloat16 g_hbf[(size_t)B_ * TL * DM];    // H bf16
__device__ __nv_bfloat16 g_wkbf[DM * DM];                // WK bf16
__device__ __nv_bfloat16 g_wqbf[DM * DM];                // WQ bf16
__device__ __nv_bfloat16 g_qbf[NC * SL * DM];            // Q bf16
__device__ __nv_bfloat16 g_wktb[(size_t)B_ * NH * TL * DK];  // tanh(k_s) [b][z][t][h]
__device__ __nv_bfloat16 g_qsb[NH * NC * SL * DK];           // q_s [z][cs][h]
__device__ __half g_ktanh[(size_t)B_ * NH * TL * DK];        // tanh(H) fp16 [b][z][t][h]

__device__ __forceinline__ float fast_tanhf(float x) {
    float xc = fminf(fmaxf(x, -15.0f), 15.0f);
    float e = __expf(2.0f * xc);
    return __fdividef(e - 1.0f, e + 1.0f);
}

__device__ __forceinline__ uint32_t h2_as_u32(__half2 h) {
    return *reinterpret_cast<uint32_t*>(&h);
}

__device__ __forceinline__ uint32_t smem_u32(const void* p) {
    return (uint32_t)__cvta_generic_to_shared(p);
}

__device__ __forceinline__ void cp_async16(uint32_t dst, const void* src) {
    asm volatile("cp.async.cg.shared.global [%0], [%1], 16;\n" ::"r"(dst), "l"(src));
}

__device__ __forceinline__ void ldsm_x4(uint32_t* r, uint32_t addr) {
    asm volatile("ldmatrix.sync.aligned.m8n8.x4.shared.b16 {%0,%1,%2,%3}, [%4];"
                 : "=r"(r[0]), "=r"(r[1]), "=r"(r[2]), "=r"(r[3])
                 : "r"(addr));
}

__device__ __forceinline__ void ldsm_x4_t(uint32_t* r, uint32_t addr) {
    asm volatile("ldmatrix.sync.aligned.m8n8.x4.trans.shared.b16 {%0,%1,%2,%3}, [%4];"
                 : "=r"(r[0]), "=r"(r[1]), "=r"(r[2]), "=r"(r[3])
                 : "r"(addr));
}

__device__ __forceinline__ void mma16816(float* c, const uint32_t* a, uint32_t b0,
                                         uint32_t b1) {
    asm volatile(
        "mma.sync.aligned.m16n8k16.row.col.f32.bf16.bf16.f32 "
        "{%0,%1,%2,%3}, {%4,%5,%6,%7}, {%8,%9}, {%0,%1,%2,%3};"
        : "+f"(c[0]), "+f"(c[1]), "+f"(c[2]), "+f"(c[3])
        : "r"(a[0]), "r"(a[1]), "r"(a[2]), "r"(a[3]), "r"(b0), "r"(b1));
}

__device__ __forceinline__ void mma16816h(float* c, const uint32_t* a, uint32_t b0,
                                          uint32_t b1) {
    asm volatile(
        "mma.sync.aligned.m16n8k16.row.col.f32.f16.f16.f32 "
        "{%0,%1,%2,%3}, {%4,%5,%6,%7}, {%8,%9}, {%0,%1,%2,%3};"
        : "+f"(c[0]), "+f"(c[1]), "+f"(c[2]), "+f"(c[3])
        : "r"(a[0]), "r"(a[1]), "r"(a[2]), "r"(a[3]), "r"(b0), "r"(b1));
}

// ---------------- fused H conversion: bf16 copy + fp16 tanh head-transposed ----------------
__global__ __launch_bounds__(256) void cvt_h_kernel(const float4* __restrict__ H4,
                                                    __nv_bfloat162* __restrict__ hbf,
                                                    __half2* __restrict__ kt) {
    int i = blockIdx.x * 256 + threadIdx.x;  // one float4 (4 dm) each
    if (i >= B_ * TL * DM / 4) return;
    float4 v = H4[i];
    hbf[2 * i] = __floats2bfloat162_rn(v.x, v.y);
    hbf[2 * i + 1] = __floats2bfloat162_rn(v.z, v.w);
    int q = i & 255;   // dm/4
    int bt = i >> 8;   // b*512+t
    int b = bt >> 9, t = bt & 511;
    int z = q >> 4, hh = (q & 15) * 4;
    size_t o = (((size_t)(b * NH + z) * TL + t) * DK + hh) >> 1;  // half2 index
    kt[o] = __floats2half2_rn(fast_tanhf(v.x), fast_tanhf(v.y));
    kt[o + 1] = __floats2half2_rn(fast_tanhf(v.z), fast_tanhf(v.w));
}

// ---------------- combined small fp32->bf16 conversions (WK, WQ, Q) ----------------
#define N4_WK (DM * DM / 4)
#define N4_Q (NC * SL * DM / 4)
__global__ __launch_bounds__(256) void cvt3_kernel(const float4* __restrict__ wk,
                                                   const float4* __restrict__ wq,
                                                   const float4* __restrict__ q) {
    int i = blockIdx.x * 256 + threadIdx.x;
    const float4* src;
    __nv_bfloat162* dst;
    int j;
    if (i < N4_WK) {
        src = wk; dst = (__nv_bfloat162*)g_wkbf; j = i;
    } else if (i < 2 * N4_WK) {
        src = wq; dst = (__nv_bfloat162*)g_wqbf; j = i - N4_WK;
    } else if (i < 2 * N4_WK + N4_Q) {
        src = q; dst = (__nv_bfloat162*)g_qbf; j = i - 2 * N4_WK;
    } else {
        return;
    }
    float4 v = src[j];
    dst[2 * j] = __floats2bfloat162_rn(v.x, v.y);
    dst[2 * j + 1] = __floats2bfloat162_rn(v.z, v.w);
}

// ---------------- Wql = ql @ WV^T  (fp32, split-K, deterministic) ----------------
__global__ __launch_bounds__(128) void wql_partial(const float* __restrict__ ql,
                                                   const float* __restrict__ WV) {
    __shared__ float sql[32 * 256];
    const int nb = blockIdx.x, kb = blockIdx.y;
    const int tid = threadIdx.x;
#pragma unroll
    for (int j = 0; j < 16; j++) {
        int idx = tid + j * 128;
        int c = idx >> 6, q = idx & 63;
        *(float4*)(sql + c * 256 + q * 4) =
            *(const float4*)(ql + c * DM + kb * 256 + q * 4);
    }
    __syncthreads();
    const int n = nb * 128 + tid;
    float acc[32];
#pragma unroll
    for (int c = 0; c < 32; c++) acc[c] = 0.f;
    const float4* wv = (const float4*)(WV + (size_t)n * DM + kb * 256);
#pragma unroll 4
    for (int k4 = 0; k4 < 64; k4++) {
        float4 w = wv[k4];
#pragma unroll
        for (int c = 0; c < 32; c++) {
            float4 qv = *(const float4*)(sql + c * 256 + k4 * 4);
            acc[c] = fmaf(w.x, qv.x, acc[c]);
            acc[c] = fmaf(w.y, qv.y, acc[c]);
            acc[c] = fmaf(w.z, qv.z, acc[c]);
            acc[c] = fmaf(w.w, qv.w, acc[c]);
        }
    }
#pragma unroll
    for (int c = 0; c < 32; c++) g_wqlp[(kb * NC + c) * DM + n] = acc[c];
}

__global__ void wql_reduce() {  // grid 32 (c), 1024 threads (n)
    int c = blockIdx.x, n = threadIdx.x;
    g_wql[c * DM + n] = ((g_wqlp[(0 * NC + c) * DM + n] + g_wqlp[(1 * NC + c) * DM + n]) +
                         (g_wqlp[(2 * NC + c) * DM + n] + g_wqlp[(3 * NC + c) * DM + n]));
}

// ---------------- bf16 tensor-core GEMM, C = A @ B^T ----------------
// MODE 0: q_s  -> g_qsb bf16 [z][m][h]
// MODE 1: tanh(k_s) -> g_wktb bf16 [b][z][t][h]
#define GSTAGES 3
#define STAGE_BYTES 32768

__device__ __forceinline__ void load_gemm_tile(uint32_t sA, uint32_t sB,
                                               const __nv_bfloat16* gA,
                                               const __nv_bfloat16* gB, int m0, int n0,
                                               int kt, int tid) {
#pragma unroll
    for (int i = 0; i < 4; i++) {
        int cid = tid + i * 256;
        int row = cid >> 3, c = cid & 7;
        uint32_t off = row * 128 + ((c * 16) ^ ((row & 7) << 4));
        cp_async16(sA + off, gA + (size_t)(m0 + row) * DM + kt * 64 + c * 8);
        cp_async16(sB + off, gB + (size_t)(n0 + row) * DM + kt * 64 + c * 8);
    }
}

template <int MODE>
__global__ __launch_bounds__(256, 2) void gemm_bf16(const __nv_bfloat16* __restrict__ A,
                                                    const __nv_bfloat16* __restrict__ Bm) {
    extern __shared__ char smem_raw[];
    const int m0 = blockIdx.y * 128, n0 = blockIdx.x * 128;
    const int tid = threadIdx.x;
    const int lane = tid & 31, wid = tid >> 5;
    const int warp_m = wid & 1, warp_n = wid >> 1;
    const uint32_t sbase = smem_u32(smem_raw);

    float acc[4][4][4];
#pragma unroll
    for (int i = 0; i < 4; i++)
#pragma unroll
        for (int j = 0; j < 4; j++)
#pragma unroll
            for (int r = 0; r < 4; r++) acc[i][j][r] = 0.f;

    const int rA = lane & 15;
    const int selA = (lane >= 16) ? 16 : 0;
    uint32_t pA[4];
#pragma unroll
    for (int mf = 0; mf < 4; mf++) {
        int row = warp_m * 64 + mf * 16 + rA;
        pA[mf] = row * 128 + (selA ^ ((row & 7) << 4));
    }
    const int rB = (lane & 7) + ((lane >= 16) ? 8 : 0);
    const int selB = (lane & 8) ? 16 : 0;
    uint32_t pB[2];
#pragma unroll
    for (int np = 0; np < 2; np++) {
        int row = warp_n * 32 + np * 16 + rB;
        pB[np] = row * 128 + (selB ^ ((row & 7) << 4));
    }

#pragma unroll
    for (int s = 0; s < GSTAGES - 1; s++) {
        load_gemm_tile(sbase + s * STAGE_BYTES, sbase + s * STAGE_BYTES + 16384, A, Bm,
                       m0, n0, s, tid);
        asm volatile("cp.async.commit_group;");
    }

    const int NT = DM / 64;
    for (int kt = 0; kt < NT; kt++) {
        asm volatile("cp.async.wait_group %0;" ::"n"(GSTAGES - 2));
        __syncthreads();
        uint32_t sA = sbase + (kt % GSTAGES) * STAGE_BYTES;
        uint32_t sB = sA + 16384;
#pragma unroll
        for (int ks = 0; ks < 4; ks++) {
            uint32_t af[4][4], bb[2][4];
#pragma unroll
            for (int mf = 0; mf < 4; mf++) ldsm_x4(af[mf], sA + (pA[mf] ^ (ks << 5)));
#pragma unroll
            for (int np = 0; np < 2; np++) ldsm_x4(bb[np], sB + (pB[np] ^ (ks << 5)));
#pragma unroll
            for (int mf = 0; mf < 4; mf++)
#pragma unroll
                for (int nf = 0; nf < 4; nf++)
                    mma16816(acc[mf][nf], af[mf], bb[nf >> 1][(nf & 1) * 2],
                             bb[nf >> 1][(nf & 1) * 2 + 1]);
        }
        int kn = kt + GSTAGES - 1;
        if (kn < NT) {
            uint32_t s = sbase + (kn % GSTAGES) * STAGE_BYTES;
            load_gemm_tile(s, s + 16384, A, Bm, m0, n0, kn, tid);
        }
        asm volatile("cp.async.commit_group;");
    }

    const int gid = lane >> 2, tig = lane & 3;
#pragma unroll
    for (int mf = 0; mf < 4; mf++) {
#pragma unroll
        for (int nf = 0; nf < 4; nf++) {
            int m = m0 + warp_m * 64 + mf * 16 + gid;
            int n = n0 + warp_n * 32 + nf * 8 + tig * 2;
            int z = n >> 6, h = n & 63;
#pragma unroll
            for (int rh = 0; rh < 2; rh++) {
                int mm = m + rh * 8;
                float v0 = acc[mf][nf][rh * 2 + 0];
                float v1 = acc[mf][nf][rh * 2 + 1];
                if (MODE == 1) {
                    int b = mm >> 9, t = mm & 511;
                    __nv_bfloat162 o = __floats2bfloat162_rn(fast_tanhf(v0), fast_tanhf(v1));
                    *(__nv_bfloat162*)(g_wktb + ((size_t)((b * NH + z) * TL + t)) * DK + h) = o;
                } else {
                    __nv_bfloat162 o = __floats2bfloat162_rn(v0, v1);
                    *(__nv_bfloat162*)(g_qsb + ((size_t)(z * (NC * SL) + mm)) * DK + h) = o;
                }
            }
        }
    }
}

// ---------------- attention: score MMA + exp + PV MMA (u = P K^T), no KW phase ----------------
// One CTA per (b, z). 512 thr = 16 warps; warp w owns classes 2w, 2w+1 (32 rows).
#define ATTN_SMEM (65536 * 3 + 8192)

__global__ __launch_bounds__(512, 1) void attn_kernel() {
    extern __shared__ char sm[];
    __nv_bfloat16* sQb = (__nv_bfloat16*)sm;             // [cs][h] bf16 swizzled, 64 KB
    __nv_bfloat16* sWKb = (__nv_bfloat16*)(sm + 65536);  // [t][h] bf16 swizzled, 64 KB
    __half* sKtb = (__half*)(sm + 131072);               // [t][h] fp16 swizzled, 64 KB
    float* sWql = (float*)(sm + 196608);                 // [c][64] fp32, 8 KB

    const int z = blockIdx.x, b = blockIdx.y;
    const int tid = threadIdx.x, lane = tid & 31, w = tid >> 5;
    const uint32_t sQ_u = smem_u32(sQb), sWK_u = smem_u32(sWKb), sKt_u = smem_u32(sKtb);

    {
        const char* gq = (const char*)(g_qsb + (size_t)z * (NC * SL) * DK);
        const char* gwk = (const char*)(g_wktb + (size_t)(b * NH + z) * TL * DK);
        const char* gkt = (const char*)(g_ktanh + (size_t)(b * NH + z) * TL * DK);
#pragma unroll
        for (int i = 0; i < 8; i++) {
            int cid = tid + i * 512;
            int row = cid >> 3, cc = cid & 7;
            uint32_t off = row * 128 + ((cc * 16) ^ ((row & 7) << 4));
            cp_async16(sQ_u + off, gq + row * 128 + cc * 16);
            cp_async16(sWK_u + off, gwk + row * 128 + cc * 16);
            cp_async16(sKt_u + off, gkt + row * 128 + cc * 16);
        }
        int c = tid >> 4, q = tid & 15;
        cp_async16(smem_u32(sWql) + tid * 16, g_wql + c * DM + z * DK + q * 4);
        asm volatile("cp.async.commit_group;");
        asm volatile("cp.async.wait_group 0;");
    }
    __syncthreads();

    // score A fragment base addrs (rows 32w..32w+31 of q_s)
    const int rA = lane & 15;
    const int selA = (lane >= 16) ? 16 : 0;
    uint32_t pA[2];
#pragma unroll
    for (int mf = 0; mf < 2; mf++) {
        int row = w * 32 + mf * 16 + rA;
        pA[mf] = row * 128 + (selA ^ ((row & 7) << 4));
    }
    // score B lane offsets (rows = t)
    const int rB = (lane & 7) + ((lane >= 16) ? 8 : 0);
    const int selB = (lane & 8) ? 16 : 0;
    // PV B (ldsm.trans) lane offsets: row = t0 + (lane&15), 16B-col = (lane>>4)&1
    const int rT = lane & 15;
    const int cT = ((lane >> 4) & 1) * 16;
    const int tig = lane & 3;

    float l[2][2] = {{0.f, 0.f}, {0.f, 0.f}};
    float u[2][8][4];
#pragma unroll
    for (int mf = 0; mf < 2; mf++)
#pragma unroll
        for (int nc = 0; nc < 8; nc++)
#pragma unroll
            for (int r = 0; r < 4; r++) u[mf][nc][r] = 0.f;

    for (int hc = 0; hc < 32; hc++) {  // 32 half-chunks of 16 t
        const int t0 = hc * 16;
        // ---- scores S[32 rows x 16 t] ----
        float acc[2][2][4];
#pragma unroll
        for (int mf = 0; mf < 2; mf++)
#pragma unroll
            for (int nf = 0; nf < 2; nf++)
#pragma unroll
                for (int r = 0; r < 4; r++) acc[mf][nf][r] = 0.f;

#pragma unroll
        for (int ks = 0; ks < 4; ks++) {
            uint32_t bb[4], af[2][4];
            {
                int row = t0 + rB;
                uint32_t p = row * 128 + (selB ^ ((row & 7) << 4));
                ldsm_x4(bb, sWK_u + (p ^ (ks << 5)));
            }
#pragma unroll
            for (int mf = 0; mf < 2; mf++) ldsm_x4(af[mf], sQ_u + (pA[mf] ^ (ks << 5)));
#pragma unroll
            for (int mf = 0; mf < 2; mf++)
#pragma unroll
                for (int nf = 0; nf < 2; nf++)
                    mma16816(acc[mf][nf], af[mf], bb[nf * 2], bb[nf * 2 + 1]);
        }

        // ---- exp (no max-subtract: scores tiny) + pack P fp16 + accumulate l ----
        uint32_t pa[2][4];
#pragma unroll
        for (int mf = 0; mf < 2; mf++) {
#pragma unroll
            for (int nf = 0; nf < 2; nf++) {
                float p0 = __expf(acc[mf][nf][0]);
                float p1 = __expf(acc[mf][nf][1]);
                float p2 = __expf(acc[mf][nf][2]);
                float p3 = __expf(acc[mf][nf][3]);
                l[mf][0] += p0 + p1;
                l[mf][1] += p2 + p3;
                pa[mf][nf * 2 + 0] = h2_as_u32(__floats2half2_rn(p0, p1));
                pa[mf][nf * 2 + 1] = h2_as_u32(__floats2half2_rn(p2, p3));
            }
        }

        // ---- PV: u[rows x 64 h] += P[rows x 16 t] * Ktanh[16 t x 64 h] ----
        {
            int row = t0 + rT;
            uint32_t pbase = row * 128 + ((row & 7) << 4);
#pragma unroll
            for (int h16 = 0; h16 < 4; h16++) {
                uint32_t bt[4];
                ldsm_x4_t(bt, sKt_u + (pbase ^ (h16 * 32 + cT)));
#pragma unroll
                for (int mf = 0; mf < 2; mf++) {
                    mma16816h(u[mf][h16 * 2 + 0], pa[mf], bt[0], bt[1]);
                    mma16816h(u[mf][h16 * 2 + 1], pa[mf], bt[2], bt[3]);
                }
            }
        }
    }

    // ---- v = sum_h u * wql (fp32), divide, mean over s, write ----
#pragma unroll
    for (int mf = 0; mf < 2; mf++) {
        const int c = 2 * w + mf;
        float r = 0.f;
#pragma unroll
        for (int rh = 0; rh < 2; rh++) {
            float vv = 0.f;
#pragma unroll
            for (int nc = 0; nc < 8; nc++) {
                float2 wq = *(const float2*)(sWql + c * 64 + nc * 8 + tig * 2);
                vv = fmaf(u[mf][nc][rh * 2 + 0], wq.x,
                          fmaf(u[mf][nc][rh * 2 + 1], wq.y, vv));
            }
            float ll = l[mf][rh];
#pragma unroll
            for (int off = 1; off <= 2; off <<= 1) {
                vv += __shfl_xor_sync(0xffffffffu, vv, off);
                ll += __shfl_xor_sync(0xffffffffu, ll, off);
            }
            r += __fdividef(vv, ll);
        }
#pragma unroll
        for (int off = 4; off <= 16; off <<= 1) r += __shfl_xor_sync(0xffffffffu, r, off);
        if (lane == 0) g_partial[(b * NH + z) * NC + c] = r * (1.0f / 16.0f);
    }
}

__global__ void reduce_out(float* __restrict__ out) {
    int tid = threadIdx.x;
    int b = tid >> 5, c = tid & 31;
    float s = 0.f;
#pragma unroll
    for (int zz = 0; zz < NH; zz++) s += g_partial[(b * NH + zz) * NC + c];
    out[tid] = s;
}

extern "C" void kernel_launch(void* const* d_in, const int* in_sizes, int n_in,
                              void* d_out, int out_size) {
    const float* Q = (const float*)d_in[0];
    const float* H = (const float*)d_in[1];
    const float* ql = (const float*)d_in[2];
    const float* WQ = (const float*)d_in[3];
    const float* WK = (const float*)d_in[4];
    const float* WV = (const float*)d_in[5];
    float* out = (float*)d_out;

    cudaFuncSetAttribute(attn_kernel, cudaFuncAttributeMaxDynamicSharedMemorySize,
                         ATTN_SMEM);
    cudaFuncSetAttribute(gemm_bf16<0>, cudaFuncAttributeMaxDynamicSharedMemorySize,
                         GSTAGES * STAGE_BYTES);
    cudaFuncSetAttribute(gemm_bf16<1>, cudaFuncAttributeMaxDynamicSharedMemorySize,
                         GSTAGES * STAGE_BYTES);

    __nv_bfloat16 *hbf, *wkbf, *wqbf, *qbf;
    __half* ktanh;
    cudaGetSymbolAddress((void**)&hbf, g_hbf);
    cudaGetSymbolAddress((void**)&wkbf, g_wkbf);
    cudaGetSymbolAddress((void**)&wqbf, g_wqbf);
    cudaGetSymbolAddress((void**)&qbf, g_qbf);
    cudaGetSymbolAddress((void**)&ktanh, g_ktanh);

    cvt_h_kernel<<<(B_ * TL * DM / 4 + 255) / 256, 256>>>(
        (const float4*)H, (__nv_bfloat162*)hbf, (__half2*)ktanh);
    cvt3_kernel<<<(2 * N4_WK + N4_Q + 255) / 256, 256>>>(
        (const float4*)WK, (const float4*)WQ, (const float4*)Q);

    wql_partial<<<dim3(8, 4), 128>>>(ql, WV);
    wql_reduce<<<32, 1024>>>();

    gemm_bf16<0><<<dim3(8, 4), 256, GSTAGES * STAGE_BYTES>>>(qbf, wqbf);
    gemm_bf16<1><<<dim3(8, 128), 256, GSTAGES * STAGE_BYTES>>>(hbf, wkbf);

    attn_kernel<<<dim3(NH, B_), 512, ATTN_SMEM>>>();
    reduce_out<<<1, 1024>>>(out);
}